// round 15
// baseline (speedup 1.0000x reference)
#include <cuda_runtime.h>
#include <cuda_bf16.h>
#include <cstdint>

// Problem constants
#define N_EDGES   32768
#define N_NODES   2048
#define D_FEAT    32
#define D_CAT     160
#define NODE_CAP  512
#define EDGE_CAP  64

// ---------------- scratch (static device globals; no allocation) -------------
__device__ float g_s[N_EDGES * 128];              // s = memory MLP output (fp32)
__device__ float g_nodesum[N_NODES * 128];        // mask @ s
__device__ __nv_bfloat16 g_agg_hi[N_EDGES * D_CAT];  // pre-split [agg | feature]
__device__ __nv_bfloat16 g_agg_lo[N_EDGES * D_CAT];
__device__ __nv_bfloat16 g_w1m_hi[128 * 128], g_w1m_lo[128 * 128];
__device__ __nv_bfloat16 g_w2m_hi[128 * 128], g_w2m_lo[128 * 128];
__device__ __nv_bfloat16 g_w1a_hi[128 * 160], g_w1a_lo[128 * 160];
__device__ __nv_bfloat16 g_w2a_hi[128 * 128], g_w2a_lo[128 * 128];
__device__ int   g_node_cnt[N_NODES];
__device__ int   g_node_edges[N_NODES * NODE_CAP];
__device__ int   g_edge_cnt[N_EDGES];
__device__ int   g_edge_nodes[N_EDGES * EDGE_CAP];

// ---------------- small helpers ----------------------------------------------
__device__ __forceinline__ float log_sigmoid(float x) {
    return fminf(x, 0.0f) - log1pf(__expf(-fabsf(x)));
}

__device__ __forceinline__ uint32_t smem_u32(const void* p) {
    uint32_t a;
    asm("{ .reg .u64 t; cvta.to.shared.u64 t, %1; cvt.u32.u64 %0, t; }" : "=r"(a) : "l"(p));
    return a;
}

__device__ __forceinline__ uint32_t pack2(__nv_bfloat16 a, __nv_bfloat16 b) {
    __nv_bfloat162 p;
    p.x = a; p.y = b;
    return *reinterpret_cast<uint32_t*>(&p);
}

__device__ __forceinline__ void ldm_x4(uint32_t* r, uint32_t addr) {
    asm volatile("ldmatrix.sync.aligned.m8n8.x4.shared.b16 {%0,%1,%2,%3}, [%4];"
                 : "=r"(r[0]), "=r"(r[1]), "=r"(r[2]), "=r"(r[3]) : "r"(addr));
}

__device__ __forceinline__ void mma16816(float* c, const uint32_t* a, uint32_t b0, uint32_t b1) {
    asm volatile("mma.sync.aligned.m16n8k16.row.col.f32.bf16.bf16.f32 "
                 "{%0,%1,%2,%3}, {%4,%5,%6,%7}, {%8,%9}, {%0,%1,%2,%3};"
                 : "+f"(c[0]), "+f"(c[1]), "+f"(c[2]), "+f"(c[3])
                 : "r"(a[0]), "r"(a[1]), "r"(a[2]), "r"(a[3]), "r"(b0), "r"(b1));
}

__device__ __forceinline__ void cp16(uint32_t dst, const void* src) {
    asm volatile("cp.async.cg.shared.global [%0], [%1], 16;" :: "r"(dst), "l"(src));
}
__device__ __forceinline__ void cp_commit_wait() {
    asm volatile("cp.async.commit_group;" ::: "memory");
    asm volatile("cp.async.wait_group 0;" ::: "memory");
}

// 3-product pass with both W matrices resident (used by MLP-A).
template <int NK>
__device__ __forceinline__ void mma_block(
    uint32_t aHi, uint32_t aLo, uint32_t bHi, uint32_t bLo,
    uint32_t ldkB, float (*acc)[4][4])
{
    #pragma unroll
    for (int ks = 0; ks < NK; ks++) {
        const uint32_t koff = (uint32_t)ks * 32;
        uint32_t ah[2][4], al[2][4], bh[2][4], bl[2][4];
        #pragma unroll
        for (int mf = 0; mf < 2; mf++) {
            ldm_x4(ah[mf], aHi + koff + (uint32_t)mf * 16 * ldkB);
            ldm_x4(al[mf], aLo + koff + (uint32_t)mf * 16 * ldkB);
        }
        #pragma unroll
        for (int g = 0; g < 2; g++) {
            ldm_x4(bh[g], bHi + koff + (uint32_t)g * 16 * ldkB);
            ldm_x4(bl[g], bLo + koff + (uint32_t)g * 16 * ldkB);
        }
        #pragma unroll
        for (int mf = 0; mf < 2; mf++) {
            #pragma unroll
            for (int nf = 0; nf < 4; nf++) {
                const int g = nf >> 1, h = (nf & 1) * 2;
                mma16816(acc[mf][nf], ah[mf], bh[g][h], bh[g][h + 1]);
                mma16816(acc[mf][nf], ah[mf], bl[g][h], bl[g][h + 1]);
                mma16816(acc[mf][nf], al[mf], bh[g][h], bh[g][h + 1]);
            }
        }
    }
}

// Pass with a single W matrix resident: acc += Ahi@W^T (+ Alo@W^T if USE_AL).
template <int NK, bool USE_AL>
__device__ __forceinline__ void mma_block_w(
    uint32_t aHi, uint32_t aLo, uint32_t bW, uint32_t ldkB, float (*acc)[4][4])
{
    #pragma unroll
    for (int ks = 0; ks < NK; ks++) {
        const uint32_t koff = (uint32_t)ks * 32;
        uint32_t ah[2][4], al[2][4], bw[2][4];
        #pragma unroll
        for (int mf = 0; mf < 2; mf++) {
            ldm_x4(ah[mf], aHi + koff + (uint32_t)mf * 16 * ldkB);
            if (USE_AL) ldm_x4(al[mf], aLo + koff + (uint32_t)mf * 16 * ldkB);
        }
        #pragma unroll
        for (int g = 0; g < 2; g++)
            ldm_x4(bw[g], bW + koff + (uint32_t)g * 16 * ldkB);
        #pragma unroll
        for (int mf = 0; mf < 2; mf++) {
            #pragma unroll
            for (int nf = 0; nf < 4; nf++) {
                const int g = nf >> 1, h = (nf & 1) * 2;
                mma16816(acc[mf][nf], ah[mf], bw[g][h], bw[g][h + 1]);
                if (USE_AL) mma16816(acc[mf][nf], al[mf], bw[g][h], bw[g][h + 1]);
            }
        }
    }
}

// ---------------- kernel: zero edge counters ---------------------------------
__global__ void zero_edge_cnt_kernel() {
    int i = blockIdx.x * blockDim.x + threadIdx.x;
    if (i < N_EDGES) g_edge_cnt[i] = 0;
}

// ---------------- kernel: split weights into bf16 hi/lo ----------------------
__global__ void prep_weights_kernel(const float* __restrict__ w1m,
                                    const float* __restrict__ w2m,
                                    const float* __restrict__ w1a,
                                    const float* __restrict__ w2a) {
    int i = blockIdx.x * blockDim.x + threadIdx.x;
    if (i < 128 * 128) {
        float v = w1m[i];
        __nv_bfloat16 h = __float2bfloat16(v);
        g_w1m_hi[i] = h; g_w1m_lo[i] = __float2bfloat16(v - __bfloat162float(h));
        v = w2m[i]; h = __float2bfloat16(v);
        g_w2m_hi[i] = h; g_w2m_lo[i] = __float2bfloat16(v - __bfloat162float(h));
        v = w2a[i]; h = __float2bfloat16(v);
        g_w2a_hi[i] = h; g_w2a_lo[i] = __float2bfloat16(v - __bfloat162float(h));
    }
    if (i < 128 * 160) {
        float v = w1a[i];
        __nv_bfloat16 h = __float2bfloat16(v);
        g_w1a_hi[i] = h; g_w1a_lo[i] = __float2bfloat16(v - __bfloat162float(h));
    }
}

// ---------------- kernel: fused 2-layer MLP, both W pairs resident (K=128) ---
__global__ void __launch_bounds__(256, 2)
fused_mlp_kernel(const float* __restrict__ Af,
                 const __nv_bfloat16* __restrict__ W1hi,
                 const __nv_bfloat16* __restrict__ W1lo,
                 const float* __restrict__ b1,
                 const __nv_bfloat16* __restrict__ W2hi,
                 const __nv_bfloat16* __restrict__ W2lo,
                 float* __restrict__ Cout) {
    extern __shared__ char sm[];
    constexpr int K1 = 128, LDK1 = 136, LDK2 = 136;
    constexpr int TA = 64 * LDK1 * 2;
    constexpr int TW = 128 * LDK1 * 2;
    float*         s_bias = reinterpret_cast<float*>(sm);
    __nv_bfloat16* sAhi = reinterpret_cast<__nv_bfloat16*>(sm + 512);
    __nv_bfloat16* sAlo = reinterpret_cast<__nv_bfloat16*>(sm + 512 + TA);
    __nv_bfloat16* sWhi = reinterpret_cast<__nv_bfloat16*>(sm + 512 + 2 * TA);
    __nv_bfloat16* sWlo = reinterpret_cast<__nv_bfloat16*>(sm + 512 + 2 * TA + TW);

    const int tid  = threadIdx.x;
    const int wid  = tid >> 5;
    const int lane = tid & 31;
    const int row0 = blockIdx.x * 64;
    const uint32_t uAhi = smem_u32(sAhi), uAlo = smem_u32(sAlo);
    const uint32_t uWhi = smem_u32(sWhi), uWlo = smem_u32(sWlo);

    if (tid < 128) s_bias[tid] = b1[tid];

    // --- W1 via cp.async ---
    for (int idx = tid; idx < 128 * 16; idx += 256) {
        int row = idx >> 4, ko = (idx & 15) * 8;
        uint32_t d = (uint32_t)(row * LDK1 + ko) * 2;
        cp16(uWhi + d, W1hi + (size_t)row * K1 + ko);
        cp16(uWlo + d, W1lo + (size_t)row * K1 + ko);
    }
    // --- A tile: fp32 -> split bf16 ---
    {
        const float4* a4 = reinterpret_cast<const float4*>(Af + (size_t)row0 * K1);
        for (int idx = tid; idx < 64 * 32; idx += 256) {
            int row = idx >> 5, k0 = (idx & 31) * 4;
            float4 v = a4[idx];
            __nv_bfloat16 h0 = __float2bfloat16(v.x), h1 = __float2bfloat16(v.y);
            __nv_bfloat16 h2 = __float2bfloat16(v.z), h3 = __float2bfloat16(v.w);
            __nv_bfloat16 l0 = __float2bfloat16(v.x - __bfloat162float(h0));
            __nv_bfloat16 l1 = __float2bfloat16(v.y - __bfloat162float(h1));
            __nv_bfloat16 l2 = __float2bfloat16(v.z - __bfloat162float(h2));
            __nv_bfloat16 l3 = __float2bfloat16(v.w - __bfloat162float(h3));
            uint32_t* ph = reinterpret_cast<uint32_t*>(&sAhi[row * LDK1 + k0]);
            uint32_t* pl = reinterpret_cast<uint32_t*>(&sAlo[row * LDK1 + k0]);
            ph[0] = pack2(h0, h1); ph[1] = pack2(h2, h3);
            pl[0] = pack2(l0, l1); pl[1] = pack2(l2, l3);
        }
    }
    cp_commit_wait();
    __syncthreads();

    const int wm = wid >> 2, wn = wid & 3;
    const int rl = lane >> 2, cl = (lane & 3) * 2;
    const int arow = wm * 32 + (lane & 7) + ((lane >> 3) & 1) * 8;
    const int acol = (lane >> 4) * 8;
    const int brow = wn * 32 + (lane & 7) + ((lane >> 4) & 1) * 8;
    const int bcol = ((lane >> 3) & 1) * 8;

    float acc[2][4][4];
    #pragma unroll
    for (int i = 0; i < 2; i++)
        #pragma unroll
        for (int j = 0; j < 4; j++)
            #pragma unroll
            for (int e = 0; e < 4; e++) acc[i][j][e] = 0.0f;

    mma_block<8>(uAhi + (uint32_t)(arow * LDK1 + acol) * 2,
                 uAlo + (uint32_t)(arow * LDK1 + acol) * 2,
                 uWhi + (uint32_t)(brow * LDK1 + bcol) * 2,
                 uWlo + (uint32_t)(brow * LDK1 + bcol) * 2,
                 (uint32_t)LDK1 * 2, acc);
    __syncthreads();

    // W2 replaces W1
    for (int idx = tid; idx < 128 * 16; idx += 256) {
        int row = idx >> 4, ko = (idx & 15) * 8;
        uint32_t d = (uint32_t)(row * LDK2 + ko) * 2;
        cp16(uWhi + d, W2hi + (size_t)row * 128 + ko);
        cp16(uWlo + d, W2lo + (size_t)row * 128 + ko);
    }
    // bias + ls, split h into A buffers
    #pragma unroll
    for (int mf = 0; mf < 2; mf++)
        #pragma unroll
        for (int nf = 0; nf < 4; nf++) {
            const int c0 = wn * 32 + nf * 8 + cl;
            const float b0 = s_bias[c0], b1v = s_bias[c0 + 1];
            #pragma unroll
            for (int half = 0; half < 2; half++) {
                const int row = wm * 32 + mf * 16 + rl + half * 8;
                float v0 = log_sigmoid(acc[mf][nf][half * 2 + 0] + b0);
                float v1 = log_sigmoid(acc[mf][nf][half * 2 + 1] + b1v);
                __nv_bfloat16 h0 = __float2bfloat16(v0);
                __nv_bfloat16 h1 = __float2bfloat16(v1);
                __nv_bfloat16 l0 = __float2bfloat16(v0 - __bfloat162float(h0));
                __nv_bfloat16 l1 = __float2bfloat16(v1 - __bfloat162float(h1));
                *reinterpret_cast<uint32_t*>(&sAhi[row * LDK2 + c0]) = pack2(h0, h1);
                *reinterpret_cast<uint32_t*>(&sAlo[row * LDK2 + c0]) = pack2(l0, l1);
            }
        }
    cp_commit_wait();
    __syncthreads();

    #pragma unroll
    for (int i = 0; i < 2; i++)
        #pragma unroll
        for (int j = 0; j < 4; j++)
            #pragma unroll
            for (int e = 0; e < 4; e++) acc[i][j][e] = 0.0f;

    mma_block<8>(uAhi + (uint32_t)(arow * LDK2 + acol) * 2,
                 uAlo + (uint32_t)(arow * LDK2 + acol) * 2,
                 uWhi + (uint32_t)(brow * LDK2 + bcol) * 2,
                 uWlo + (uint32_t)(brow * LDK2 + bcol) * 2,
                 (uint32_t)LDK2 * 2, acc);

    #pragma unroll
    for (int mf = 0; mf < 2; mf++)
        #pragma unroll
        for (int nf = 0; nf < 4; nf++) {
            const int c0 = wn * 32 + nf * 8 + cl;
            #pragma unroll
            for (int half = 0; half < 2; half++) {
                const int rg = row0 + wm * 32 + mf * 16 + rl + half * 8;
                float v0 = log_sigmoid(acc[mf][nf][half * 2 + 0]);
                float v1 = log_sigmoid(acc[mf][nf][half * 2 + 1]);
                *reinterpret_cast<float2*>(Cout + (size_t)rg * 128 + c0) =
                    make_float2(v0, v1);
            }
        }
}

// ---------------- kernel: fused 2-layer MLP, W streamed one-at-a-time --------
// K1=160 (agg MLP). Smem = bias + A hi/lo (full K) + ONE W panel => 86.5 KB
// => 2 CTAs/SM (vs 1 with both W pairs resident). Product passes:
//   P1: ah*W1hi + al*W1hi   (W buffer = W1hi)
//   P2: ah*W1lo             (swap W buffer)
//   P3: hh*W2hi + hl*W2hi
//   P4: hh*W2lo
__global__ void __launch_bounds__(256, 2)
fused_mlp_wsplit_kernel(const __nv_bfloat16* __restrict__ Ahi,
                        const __nv_bfloat16* __restrict__ Alo,
                        const __nv_bfloat16* __restrict__ W1hi,
                        const __nv_bfloat16* __restrict__ W1lo,
                        const float* __restrict__ b1,
                        const __nv_bfloat16* __restrict__ W2hi,
                        const __nv_bfloat16* __restrict__ W2lo,
                        float* __restrict__ Cout) {
    extern __shared__ char sm[];
    constexpr int K1 = 160, LDK1 = 168, LDK2 = 136;
    constexpr int TA = 64 * LDK1 * 2;     // 21504 B
    float*         s_bias = reinterpret_cast<float*>(sm);
    __nv_bfloat16* sAhi = reinterpret_cast<__nv_bfloat16*>(sm + 512);
    __nv_bfloat16* sAlo = reinterpret_cast<__nv_bfloat16*>(sm + 512 + TA);
    __nv_bfloat16* sW   = reinterpret_cast<__nv_bfloat16*>(sm + 512 + 2 * TA);

    const int tid  = threadIdx.x;
    const int wid  = tid >> 5;
    const int lane = tid & 31;
    const int row0 = blockIdx.x * 64;
    const uint32_t uAhi = smem_u32(sAhi), uAlo = smem_u32(sAlo);
    const uint32_t uW = smem_u32(sW);

    if (tid < 128) s_bias[tid] = b1[tid];

    // W1hi + A (pre-split) via cp.async
    for (int idx = tid; idx < 128 * 20; idx += 256) {
        int row = idx / 20, ko = (idx % 20) * 8;
        cp16(uW + (uint32_t)(row * LDK1 + ko) * 2, W1hi + (size_t)row * K1 + ko);
    }
    for (int idx = tid; idx < 64 * 20; idx += 256) {
        int row = idx / 20, ko = (idx % 20) * 8;
        uint32_t d = (uint32_t)(row * LDK1 + ko) * 2;
        cp16(uAhi + d, Ahi + (size_t)(row0 + row) * K1 + ko);
        cp16(uAlo + d, Alo + (size_t)(row0 + row) * K1 + ko);
    }
    cp_commit_wait();
    __syncthreads();

    const int wm = wid >> 2, wn = wid & 3;
    const int rl = lane >> 2, cl = (lane & 3) * 2;
    const int arow = wm * 32 + (lane & 7) + ((lane >> 3) & 1) * 8;
    const int acol = (lane >> 4) * 8;
    const int brow = wn * 32 + (lane & 7) + ((lane >> 4) & 1) * 8;
    const int bcol = ((lane >> 3) & 1) * 8;

    float acc[2][4][4];
    #pragma unroll
    for (int i = 0; i < 2; i++)
        #pragma unroll
        for (int j = 0; j < 4; j++)
            #pragma unroll
            for (int e = 0; e < 4; e++) acc[i][j][e] = 0.0f;

    const uint32_t a1h = uAhi + (uint32_t)(arow * LDK1 + acol) * 2;
    const uint32_t a1l = uAlo + (uint32_t)(arow * LDK1 + acol) * 2;
    const uint32_t w1  = uW   + (uint32_t)(brow * LDK1 + bcol) * 2;

    // P1: (ah + al) * W1hi
    mma_block_w<10, true>(a1h, a1l, w1, (uint32_t)LDK1 * 2, acc);
    __syncthreads();
    // swap in W1lo
    for (int idx = tid; idx < 128 * 20; idx += 256) {
        int row = idx / 20, ko = (idx % 20) * 8;
        cp16(uW + (uint32_t)(row * LDK1 + ko) * 2, W1lo + (size_t)row * K1 + ko);
    }
    cp_commit_wait();
    __syncthreads();
    // P2: ah * W1lo
    mma_block_w<10, false>(a1h, a1l, w1, (uint32_t)LDK1 * 2, acc);
    __syncthreads();

    // swap in W2hi (stride LDK2) + write h split into A buffers (stride LDK2)
    for (int idx = tid; idx < 128 * 16; idx += 256) {
        int row = idx >> 4, ko = (idx & 15) * 8;
        cp16(uW + (uint32_t)(row * LDK2 + ko) * 2, W2hi + (size_t)row * 128 + ko);
    }
    #pragma unroll
    for (int mf = 0; mf < 2; mf++)
        #pragma unroll
        for (int nf = 0; nf < 4; nf++) {
            const int c0 = wn * 32 + nf * 8 + cl;
            const float b0 = s_bias[c0], b1v = s_bias[c0 + 1];
            #pragma unroll
            for (int half = 0; half < 2; half++) {
                const int row = wm * 32 + mf * 16 + rl + half * 8;
                float v0 = log_sigmoid(acc[mf][nf][half * 2 + 0] + b0);
                float v1 = log_sigmoid(acc[mf][nf][half * 2 + 1] + b1v);
                __nv_bfloat16 h0 = __float2bfloat16(v0);
                __nv_bfloat16 h1 = __float2bfloat16(v1);
                __nv_bfloat16 l0 = __float2bfloat16(v0 - __bfloat162float(h0));
                __nv_bfloat16 l1 = __float2bfloat16(v1 - __bfloat162float(h1));
                *reinterpret_cast<uint32_t*>(&sAhi[row * LDK2 + c0]) = pack2(h0, h1);
                *reinterpret_cast<uint32_t*>(&sAlo[row * LDK2 + c0]) = pack2(l0, l1);
            }
        }
    cp_commit_wait();
    __syncthreads();

    #pragma unroll
    for (int i = 0; i < 2; i++)
        #pragma unroll
        for (int j = 0; j < 4; j++)
            #pragma unroll
            for (int e = 0; e < 4; e++) acc[i][j][e] = 0.0f;

    const uint32_t a2h = uAhi + (uint32_t)(arow * LDK2 + acol) * 2;
    const uint32_t a2l = uAlo + (uint32_t)(arow * LDK2 + acol) * 2;
    const uint32_t w2  = uW   + (uint32_t)(brow * LDK2 + bcol) * 2;

    // P3: (hh + hl) * W2hi
    mma_block_w<8, true>(a2h, a2l, w2, (uint32_t)LDK2 * 2, acc);
    __syncthreads();
    for (int idx = tid; idx < 128 * 16; idx += 256) {
        int row = idx >> 4, ko = (idx & 15) * 8;
        cp16(uW + (uint32_t)(row * LDK2 + ko) * 2, W2lo + (size_t)row * 128 + ko);
    }
    cp_commit_wait();
    __syncthreads();
    // P4: hh * W2lo
    mma_block_w<8, false>(a2h, a2l, w2, (uint32_t)LDK2 * 2, acc);

    #pragma unroll
    for (int mf = 0; mf < 2; mf++)
        #pragma unroll
        for (int nf = 0; nf < 4; nf++) {
            const int c0 = wn * 32 + nf * 8 + cl;
            #pragma unroll
            for (int half = 0; half < 2; half++) {
                const int rg = row0 + wm * 32 + mf * 16 + rl + half * 8;
                float v0 = log_sigmoid(acc[mf][nf][half * 2 + 0]);
                float v1 = log_sigmoid(acc[mf][nf][half * 2 + 1]);
                *reinterpret_cast<float2*>(Cout + (size_t)rg * 128 + c0) =
                    make_float2(v0, v1);
            }
        }
}

// ---------------- kernel: persistent mask scan, build adjacency --------------
// Grid 512 (NOT 2048): ~3.5 blocks/SM => ~28K regs used, leaving register
// room for one fused-MLP CTA (32.5K regs) to co-reside on every SM. This is
// what makes the graph-fork overlap actually happen (R13's 2048-block launch
// filled the regfile and serialized the branches).
__global__ void __launch_bounds__(256)
build_lists_kernel(const float* __restrict__ mask) {
    __shared__ int s_scan[256];
    const int tid = threadIdx.x;

    for (int rep = 0; rep < 4; rep++) {
        const int n = blockIdx.x + 512 * rep;
        const uint4* mrow = reinterpret_cast<const uint4*>(mask + (size_t)n * N_EDGES);

        int local[16];
        int c = 0;
        #pragma unroll 4
        for (int i = tid; i < N_EDGES / 4; i += 256) {
            uint4 v = __ldcs(&mrow[i]);
            if (v.x | v.y | v.z | v.w) {
                int e = i * 4;
                if (v.x) { if (c < 16) local[c] = e + 0; c++; }
                if (v.y) { if (c < 16) local[c] = e + 1; c++; }
                if (v.z) { if (c < 16) local[c] = e + 2; c++; }
                if (v.w) { if (c < 16) local[c] = e + 3; c++; }
            }
        }
        c = min(c, 16);

        __syncthreads();   // s_scan reuse across reps
        s_scan[tid] = c;
        __syncthreads();
        #pragma unroll
        for (int off = 1; off < 256; off <<= 1) {
            int v = (tid >= off) ? s_scan[tid - off] : 0;
            __syncthreads();
            s_scan[tid] += v;
            __syncthreads();
        }
        int offset = s_scan[tid] - c;
        int total  = s_scan[255];

        for (int j = 0; j < c; j++) {
            int e   = local[j];
            int pos = offset + j;
            if (pos < NODE_CAP) g_node_edges[n * NODE_CAP + pos] = e;
            int q = atomicAdd(&g_edge_cnt[e], 1);
            if (q < EDGE_CAP) g_edge_nodes[e * EDGE_CAP + q] = n;
        }
        if (tid == 0) g_node_cnt[n] = min(total, NODE_CAP);
    }
}

// ---------------- kernel: nodesum[n] = sum_{e in list(n)} s[e] ---------------
__global__ void __launch_bounds__(128)
node_sum_kernel() {
    const int n = blockIdx.x;
    const int d = threadIdx.x;
    const int cnt = g_node_cnt[n];
    const int* lst = &g_node_edges[n * NODE_CAP];

    float a0 = 0.f, a1 = 0.f, a2 = 0.f, a3 = 0.f;
    int i = 0;
    for (; i + 4 <= cnt; i += 4) {
        int e0 = lst[i], e1 = lst[i + 1], e2 = lst[i + 2], e3 = lst[i + 3];
        a0 += g_s[(size_t)e0 * 128 + d];
        a1 += g_s[(size_t)e1 * 128 + d];
        a2 += g_s[(size_t)e2 * 128 + d];
        a3 += g_s[(size_t)e3 * 128 + d];
    }
    for (; i < cnt; i++) a0 += g_s[(size_t)lst[i] * 128 + d];
    g_nodesum[n * 128 + d] = (a0 + a1) + (a2 + a3);
}

// ---------------- kernel: agg + concat, written pre-split bf16 ---------------
__global__ void __launch_bounds__(128)
edge_gather_kernel(const float* __restrict__ feature) {
    const int e   = blockIdx.x;
    const int tid = threadIdx.x;

    __shared__ int sl[EDGE_CAP];
    __shared__ int ss[EDGE_CAP];
    const int cnt = min(g_edge_cnt[e], EDGE_CAP);

    if (tid < cnt) sl[tid] = g_edge_nodes[e * EDGE_CAP + tid];
    __syncthreads();
    if (tid < cnt) {
        int v = sl[tid];
        int r = 0;
        for (int j = 0; j < cnt; j++) r += (sl[j] < v);
        ss[r] = v;   // node ids unique per edge -> ranks distinct
    }
    __syncthreads();

    float acc = -g_s[(size_t)e * 128 + tid];
    for (int i = 0; i < cnt; i++)
        acc += g_nodesum[ss[i] * 128 + tid];
    {
        __nv_bfloat16 h = __float2bfloat16(acc);
        g_agg_hi[(size_t)e * D_CAT + tid] = h;
        g_agg_lo[(size_t)e * D_CAT + tid] = __float2bfloat16(acc - __bfloat162float(h));
    }
    if (tid < D_FEAT) {
        float f = feature[(size_t)e * D_FEAT + tid];
        __nv_bfloat16 h = __float2bfloat16(f);
        g_agg_hi[(size_t)e * D_CAT + 128 + tid] = h;
        g_agg_lo[(size_t)e * D_CAT + 128 + tid] = __float2bfloat16(f - __bfloat162float(h));
    }
}

// ---------------- launch -----------------------------------------------------
extern "C" void kernel_launch(void* const* d_in, const int* in_sizes, int n_in,
                              void* d_out, int out_size) {
    const float* state   = (const float*)d_in[0];
    const float* feature = (const float*)d_in[1];
    const float* mask    = (const float*)d_in[2];
    // d_in[3] = mask_transpose (unused: exactly mask.T)
    const float* W1_m    = (const float*)d_in[4];
    const float* b1_m    = (const float*)d_in[5];
    const float* W2_m    = (const float*)d_in[6];
    const float* W1_a    = (const float*)d_in[7];
    const float* b1_a    = (const float*)d_in[8];
    const float* W2_a    = (const float*)d_in[9];
    float* out = (float*)d_out;

    const int SMEM_A = 512 + 2 * (64 * 136 * 2) + 2 * (128 * 136 * 2);  // 104,960
    const int SMEM_B = 512 + 2 * (64 * 168 * 2) + (128 * 168 * 2);      //  86,528
    cudaFuncSetAttribute((const void*)fused_mlp_kernel,
                         cudaFuncAttributeMaxDynamicSharedMemorySize, SMEM_A);
    cudaFuncSetAttribute((const void*)fused_mlp_wsplit_kernel,
                         cudaFuncAttributeMaxDynamicSharedMemorySize, SMEM_B);

    float* d_s = nullptr;
    __nv_bfloat16 *d_agg_hi = nullptr, *d_agg_lo = nullptr;
    __nv_bfloat16 *d_w1mh = nullptr, *d_w1ml = nullptr, *d_w2mh = nullptr, *d_w2ml = nullptr;
    __nv_bfloat16 *d_w1ah = nullptr, *d_w1al = nullptr, *d_w2ah = nullptr, *d_w2al = nullptr;
    cudaGetSymbolAddress((void**)&d_s, g_s);
    cudaGetSymbolAddress((void**)&d_agg_hi, g_agg_hi);
    cudaGetSymbolAddress((void**)&d_agg_lo, g_agg_lo);
    cudaGetSymbolAddress((void**)&d_w1mh, g_w1m_hi);
    cudaGetSymbolAddress((void**)&d_w1ml, g_w1m_lo);
    cudaGetSymbolAddress((void**)&d_w2mh, g_w2m_hi);
    cudaGetSymbolAddress((void**)&d_w2ml, g_w2m_lo);
    cudaGetSymbolAddress((void**)&d_w1ah, g_w1a_hi);
    cudaGetSymbolAddress((void**)&d_w1al, g_w1a_lo);
    cudaGetSymbolAddress((void**)&d_w2ah, g_w2a_hi);
    cudaGetSymbolAddress((void**)&d_w2al, g_w2a_lo);

    const int GB = N_EDGES / 64;   // 512 CTAs per fused MLP

    // Fork: mask scan on side stream (persistent small grid => co-residency
    // with the MLP CTAs is physically possible this time). Host objects leak
    // by design (kernel_launch only runs for correctness + capture).
    cudaStream_t s2;
    cudaStreamCreateWithFlags(&s2, cudaStreamNonBlocking);
    cudaEvent_t evFork, evJoin;
    cudaEventCreateWithFlags(&evFork, cudaEventDisableTiming);
    cudaEventCreateWithFlags(&evJoin, cudaEventDisableTiming);

    cudaEventRecord(evFork, 0);
    cudaStreamWaitEvent(s2, evFork, 0);
    zero_edge_cnt_kernel<<<N_EDGES / 256, 256, 0, s2>>>();
    build_lists_kernel<<<512, 256, 0, s2>>>(mask);
    cudaEventRecord(evJoin, s2);

    prep_weights_kernel<<<(128 * 160 + 255) / 256, 256>>>(W1_m, W2_m, W1_a, W2_a);
    fused_mlp_kernel<<<GB, 256, SMEM_A>>>(
        state, d_w1mh, d_w1ml, b1_m, d_w2mh, d_w2ml, d_s);

    cudaStreamWaitEvent(0, evJoin, 0);
    node_sum_kernel<<<N_NODES, 128>>>();
    edge_gather_kernel<<<N_EDGES, 128>>>(feature);

    fused_mlp_wsplit_kernel<<<GB, 256, SMEM_B>>>(
        d_agg_hi, d_agg_lo, d_w1ah, d_w1al, b1_a, d_w2ah, d_w2al, out);
}

// round 17
// speedup vs baseline: 1.1161x; 1.1161x over previous
#include <cuda_runtime.h>
#include <cuda_bf16.h>
#include <cstdint>

// Problem constants
#define N_EDGES   32768
#define N_NODES   2048
#define D_FEAT    32
#define D_CAT     160
#define NODE_CAP  512
#define EDGE_CAP  64

// ---------------- scratch (static device globals; no allocation) -------------
__device__ float g_s[N_EDGES * 128];              // s = memory MLP output (fp32)
__device__ float g_nodesum[N_NODES * 128];        // mask @ s
__device__ __nv_bfloat16 g_agg_hi[N_EDGES * D_CAT];  // pre-split [agg | feature]
__device__ __nv_bfloat16 g_agg_lo[N_EDGES * D_CAT];
__device__ __nv_bfloat16 g_w1m_hi[128 * 128], g_w1m_lo[128 * 128];
__device__ __nv_bfloat16 g_w2m_hi[128 * 128], g_w2m_lo[128 * 128];
__device__ __nv_bfloat16 g_w1a_hi[128 * 160], g_w1a_lo[128 * 160];
__device__ __nv_bfloat16 g_w2a_hi[128 * 128], g_w2a_lo[128 * 128];
__device__ int   g_node_cnt[N_NODES];
__device__ int   g_node_edges[N_NODES * NODE_CAP];
__device__ int   g_edge_cnt[N_EDGES];
__device__ int   g_edge_nodes[N_EDGES * EDGE_CAP];

// ---------------- small helpers ----------------------------------------------
__device__ __forceinline__ float log_sigmoid(float x) {
    return fminf(x, 0.0f) - log1pf(__expf(-fabsf(x)));
}

__device__ __forceinline__ uint32_t smem_u32(const void* p) {
    uint32_t a;
    asm("{ .reg .u64 t; cvta.to.shared.u64 t, %1; cvt.u32.u64 %0, t; }" : "=r"(a) : "l"(p));
    return a;
}

__device__ __forceinline__ uint32_t pack2(__nv_bfloat16 a, __nv_bfloat16 b) {
    __nv_bfloat162 p;
    p.x = a; p.y = b;
    return *reinterpret_cast<uint32_t*>(&p);
}

__device__ __forceinline__ void ldm_x4(uint32_t* r, uint32_t addr) {
    asm volatile("ldmatrix.sync.aligned.m8n8.x4.shared.b16 {%0,%1,%2,%3}, [%4];"
                 : "=r"(r[0]), "=r"(r[1]), "=r"(r[2]), "=r"(r[3]) : "r"(addr));
}

__device__ __forceinline__ void mma16816(float* c, const uint32_t* a, uint32_t b0, uint32_t b1) {
    asm volatile("mma.sync.aligned.m16n8k16.row.col.f32.bf16.bf16.f32 "
                 "{%0,%1,%2,%3}, {%4,%5,%6,%7}, {%8,%9}, {%0,%1,%2,%3};"
                 : "+f"(c[0]), "+f"(c[1]), "+f"(c[2]), "+f"(c[3])
                 : "r"(a[0]), "r"(a[1]), "r"(a[2]), "r"(a[3]), "r"(b0), "r"(b1));
}

__device__ __forceinline__ void cp16(uint32_t dst, const void* src) {
    asm volatile("cp.async.cg.shared.global [%0], [%1], 16;" :: "r"(dst), "l"(src));
}
__device__ __forceinline__ void cp_commit_wait() {
    asm volatile("cp.async.commit_group;" ::: "memory");
    asm volatile("cp.async.wait_group 0;" ::: "memory");
}

// bf16-split 3-product MMA over one K panel.
// Warp tile 32x32: 2 m-frags x 4 n-frags, standard m16n8k16 fragment layouts.
template <int NK>
__device__ __forceinline__ void mma_block(
    uint32_t aHi, uint32_t aLo, uint32_t bHi, uint32_t bLo,
    uint32_t ldkB, float (*acc)[4][4])
{
    #pragma unroll
    for (int ks = 0; ks < NK; ks++) {
        const uint32_t koff = (uint32_t)ks * 32;
        uint32_t ah[2][4], al[2][4], bh[2][4], bl[2][4];
        #pragma unroll
        for (int mf = 0; mf < 2; mf++) {
            ldm_x4(ah[mf], aHi + koff + (uint32_t)mf * 16 * ldkB);
            ldm_x4(al[mf], aLo + koff + (uint32_t)mf * 16 * ldkB);
        }
        #pragma unroll
        for (int g = 0; g < 2; g++) {
            ldm_x4(bh[g], bHi + koff + (uint32_t)g * 16 * ldkB);
            ldm_x4(bl[g], bLo + koff + (uint32_t)g * 16 * ldkB);
        }
        #pragma unroll
        for (int mf = 0; mf < 2; mf++) {
            #pragma unroll
            for (int nf = 0; nf < 4; nf++) {
                const int g = nf >> 1, h = (nf & 1) * 2;
                mma16816(acc[mf][nf], ah[mf], bh[g][h], bh[g][h + 1]);
                mma16816(acc[mf][nf], ah[mf], bl[g][h], bl[g][h + 1]);
                mma16816(acc[mf][nf], al[mf], bh[g][h], bh[g][h + 1]);
            }
        }
    }
}

// ---------------- kernel: zero edge counters ---------------------------------
__global__ void zero_edge_cnt_kernel() {
    int i = blockIdx.x * blockDim.x + threadIdx.x;
    if (i < N_EDGES) g_edge_cnt[i] = 0;
}

// ---------------- kernel: split weights into bf16 hi/lo ----------------------
__global__ void prep_weights_kernel(const float* __restrict__ w1m,
                                    const float* __restrict__ w2m,
                                    const float* __restrict__ w1a,
                                    const float* __restrict__ w2a) {
    int i = blockIdx.x * blockDim.x + threadIdx.x;
    if (i < 128 * 128) {
        float v = w1m[i];
        __nv_bfloat16 h = __float2bfloat16(v);
        g_w1m_hi[i] = h; g_w1m_lo[i] = __float2bfloat16(v - __bfloat162float(h));
        v = w2m[i]; h = __float2bfloat16(v);
        g_w2m_hi[i] = h; g_w2m_lo[i] = __float2bfloat16(v - __bfloat162float(h));
        v = w2a[i]; h = __float2bfloat16(v);
        g_w2a_hi[i] = h; g_w2a_lo[i] = __float2bfloat16(v - __bfloat162float(h));
    }
    if (i < 128 * 160) {
        float v = w1a[i];
        __nv_bfloat16 h = __float2bfloat16(v);
        g_w1a_hi[i] = h; g_w1a_lo[i] = __float2bfloat16(v - __bfloat162float(h));
    }
}

// ---------------- kernel: fused 2-layer MLP (HMMA bf16-split) ----------------
// out[64-tile,128] = ls( ls( A[tile,K1] @ W1[128,K1]^T + b1 ) @ W2[128,128]^T )
// Phase 1 writes h (split bf16) into the A smem buffers; W2 replaces W1 in the
// W buffers via cp.async during the phase boundary. Grid = 512 (64-row tiles),
// 8 warps = 2(M) x 4(N), 32x32 warp tiles.
template <int K1, bool ACVT>
__global__ void __launch_bounds__(256, 2)
fused_mlp_kernel(const float* __restrict__ Af,
                 const __nv_bfloat16* __restrict__ Ahi,
                 const __nv_bfloat16* __restrict__ Alo,
                 const __nv_bfloat16* __restrict__ W1hi,
                 const __nv_bfloat16* __restrict__ W1lo,
                 const float* __restrict__ b1,
                 const __nv_bfloat16* __restrict__ W2hi,
                 const __nv_bfloat16* __restrict__ W2lo,
                 float* __restrict__ Cout) {
    extern __shared__ char sm[];
    constexpr int LDK1 = K1 + 8;
    constexpr int LDK2 = 136;
    constexpr int TA = 64 * LDK1 * 2;     // A/h buffer bytes (h needs 64*136*2 <= TA)
    constexpr int TW = 128 * LDK1 * 2;
    float*         s_bias = reinterpret_cast<float*>(sm);
    __nv_bfloat16* sAhi = reinterpret_cast<__nv_bfloat16*>(sm + 512);
    __nv_bfloat16* sAlo = reinterpret_cast<__nv_bfloat16*>(sm + 512 + TA);
    __nv_bfloat16* sWhi = reinterpret_cast<__nv_bfloat16*>(sm + 512 + 2 * TA);
    __nv_bfloat16* sWlo = reinterpret_cast<__nv_bfloat16*>(sm + 512 + 2 * TA + TW);

    const int tid  = threadIdx.x;
    const int wid  = tid >> 5;
    const int lane = tid & 31;
    const int row0 = blockIdx.x * 64;
    const uint32_t uAhi = smem_u32(sAhi), uAlo = smem_u32(sAlo);
    const uint32_t uWhi = smem_u32(sWhi), uWlo = smem_u32(sWlo);

    if (tid < 128) s_bias[tid] = b1[tid];

    // --- W1 via cp.async ---
    {
        constexpr int NC = 128 * (K1 / 8);
        for (int idx = tid; idx < NC; idx += 256) {
            int row = idx / (K1 / 8);
            int ko  = (idx % (K1 / 8)) * 8;
            uint32_t d = (uint32_t)(row * LDK1 + ko) * 2;
            cp16(uWhi + d, W1hi + (size_t)row * K1 + ko);
            cp16(uWlo + d, W1lo + (size_t)row * K1 + ko);
        }
    }
    // --- A tile ---
    if (ACVT) {
        constexpr int NV = 64 * (K1 / 4);
        const float4* a4 = reinterpret_cast<const float4*>(Af + (size_t)row0 * K1);
        for (int idx = tid; idx < NV; idx += 256) {
            int row = idx / (K1 / 4);
            int k0  = (idx % (K1 / 4)) * 4;
            float4 v = a4[idx];
            __nv_bfloat16 h0 = __float2bfloat16(v.x), h1 = __float2bfloat16(v.y);
            __nv_bfloat16 h2 = __float2bfloat16(v.z), h3 = __float2bfloat16(v.w);
            __nv_bfloat16 l0 = __float2bfloat16(v.x - __bfloat162float(h0));
            __nv_bfloat16 l1 = __float2bfloat16(v.y - __bfloat162float(h1));
            __nv_bfloat16 l2 = __float2bfloat16(v.z - __bfloat162float(h2));
            __nv_bfloat16 l3 = __float2bfloat16(v.w - __bfloat162float(h3));
            uint32_t* ph = reinterpret_cast<uint32_t*>(&sAhi[row * LDK1 + k0]);
            uint32_t* pl = reinterpret_cast<uint32_t*>(&sAlo[row * LDK1 + k0]);
            ph[0] = pack2(h0, h1); ph[1] = pack2(h2, h3);
            pl[0] = pack2(l0, l1); pl[1] = pack2(l2, l3);
        }
    } else {
        constexpr int NC = 64 * (K1 / 8);
        for (int idx = tid; idx < NC; idx += 256) {
            int row = idx / (K1 / 8);
            int ko  = (idx % (K1 / 8)) * 8;
            uint32_t d = (uint32_t)(row * LDK1 + ko) * 2;
            cp16(uAhi + d, Ahi + (size_t)(row0 + row) * K1 + ko);
            cp16(uAlo + d, Alo + (size_t)(row0 + row) * K1 + ko);
        }
    }
    cp_commit_wait();
    __syncthreads();

    const int wm = wid >> 2;         // 0..1 -> 32-row half
    const int wn = wid & 3;          // 0..3 -> 32-col quarter
    const int rl = lane >> 2;        // 0..7
    const int cl = (lane & 3) * 2;   // 0,2,4,6

    // fragment addresses (A: m16k16 x4 pattern; B: two n-halves per x4)
    const int arow = wm * 32 + (lane & 7) + ((lane >> 3) & 1) * 8;
    const int acol = (lane >> 4) * 8;
    const int brow = wn * 32 + (lane & 7) + ((lane >> 4) & 1) * 8;
    const int bcol = ((lane >> 3) & 1) * 8;

    float acc[2][4][4];
    #pragma unroll
    for (int i = 0; i < 2; i++)
        #pragma unroll
        for (int j = 0; j < 4; j++)
            #pragma unroll
            for (int e = 0; e < 4; e++) acc[i][j][e] = 0.0f;

    // ---- phase 1: h = A @ W1^T ----
    mma_block<K1 / 16>(
        uAhi + (uint32_t)(arow * LDK1 + acol) * 2,
        uAlo + (uint32_t)(arow * LDK1 + acol) * 2,
        uWhi + (uint32_t)(brow * LDK1 + bcol) * 2,
        uWlo + (uint32_t)(brow * LDK1 + bcol) * 2,
        (uint32_t)LDK1 * 2, acc);

    __syncthreads();   // all phase-1 reads of sA/sW complete

    // --- W2 via cp.async (overwrites W buffers, stride LDK2) ---
    {
        constexpr int NC = 128 * 16;   // K2/8 = 16
        for (int idx = tid; idx < NC; idx += 256) {
            int row = idx >> 4;
            int ko  = (idx & 15) * 8;
            uint32_t d = (uint32_t)(row * LDK2 + ko) * 2;
            cp16(uWhi + d, W2hi + (size_t)row * 128 + ko);
            cp16(uWlo + d, W2lo + (size_t)row * 128 + ko);
        }
    }
    // --- bias + ls, split h into A buffers (stride LDK2) ---
    #pragma unroll
    for (int mf = 0; mf < 2; mf++) {
        #pragma unroll
        for (int nf = 0; nf < 4; nf++) {
            const int c0 = wn * 32 + nf * 8 + cl;
            const float b0 = s_bias[c0], b1v = s_bias[c0 + 1];
            #pragma unroll
            for (int half = 0; half < 2; half++) {
                const int row = wm * 32 + mf * 16 + rl + half * 8;
                float v0 = log_sigmoid(acc[mf][nf][half * 2 + 0] + b0);
                float v1 = log_sigmoid(acc[mf][nf][half * 2 + 1] + b1v);
                __nv_bfloat16 h0 = __float2bfloat16(v0);
                __nv_bfloat16 h1 = __float2bfloat16(v1);
                __nv_bfloat16 l0 = __float2bfloat16(v0 - __bfloat162float(h0));
                __nv_bfloat16 l1 = __float2bfloat16(v1 - __bfloat162float(h1));
                *reinterpret_cast<uint32_t*>(&sAhi[row * LDK2 + c0]) = pack2(h0, h1);
                *reinterpret_cast<uint32_t*>(&sAlo[row * LDK2 + c0]) = pack2(l0, l1);
            }
        }
    }
    cp_commit_wait();
    __syncthreads();

    #pragma unroll
    for (int i = 0; i < 2; i++)
        #pragma unroll
        for (int j = 0; j < 4; j++)
            #pragma unroll
            for (int e = 0; e < 4; e++) acc[i][j][e] = 0.0f;

    // ---- phase 2: out = ls( h @ W2^T ) ----
    mma_block<8>(
        uAhi + (uint32_t)(arow * LDK2 + acol) * 2,
        uAlo + (uint32_t)(arow * LDK2 + acol) * 2,
        uWhi + (uint32_t)(brow * LDK2 + bcol) * 2,
        uWlo + (uint32_t)(brow * LDK2 + bcol) * 2,
        (uint32_t)LDK2 * 2, acc);

    #pragma unroll
    for (int mf = 0; mf < 2; mf++) {
        #pragma unroll
        for (int nf = 0; nf < 4; nf++) {
            const int c0 = wn * 32 + nf * 8 + cl;
            #pragma unroll
            for (int half = 0; half < 2; half++) {
                const int rg = row0 + wm * 32 + mf * 16 + rl + half * 8;
                float v0 = log_sigmoid(acc[mf][nf][half * 2 + 0]);
                float v1 = log_sigmoid(acc[mf][nf][half * 2 + 1]);
                *reinterpret_cast<float2*>(Cout + (size_t)rg * 128 + c0) =
                    make_float2(v0, v1);
            }
        }
    }
}

// ---------------- kernel: scan mask rows, build adjacency --------------------
// Fast path: 0.5% density -> P(any nonzero in 16B) ~ 2%; integer-test the
// whole float4 once, branch only on hits. Unroll for memory-level parallelism.
// 2048 blocks (NOT persistent): the scan is DRAM-bound and needs the full
// warp complement chip-wide to hold ~5.4 TB/s (R14's 512-block version lost BW).
__global__ void __launch_bounds__(256)
build_lists_kernel(const float* __restrict__ mask) {
    const int n   = blockIdx.x;
    const int tid = threadIdx.x;
    const uint4* mrow = reinterpret_cast<const uint4*>(mask + (size_t)n * N_EDGES);

    int local[16];
    int c = 0;
    #pragma unroll 4
    for (int i = tid; i < N_EDGES / 4; i += 256) {
        uint4 v = __ldcs(&mrow[i]);
        if (v.x | v.y | v.z | v.w) {
            int e = i * 4;
            if (v.x) { if (c < 16) local[c] = e + 0; c++; }
            if (v.y) { if (c < 16) local[c] = e + 1; c++; }
            if (v.z) { if (c < 16) local[c] = e + 2; c++; }
            if (v.w) { if (c < 16) local[c] = e + 3; c++; }
        }
    }
    c = min(c, 16);

    __shared__ int s_scan[256];
    s_scan[tid] = c;
    __syncthreads();
    #pragma unroll
    for (int off = 1; off < 256; off <<= 1) {
        int v = (tid >= off) ? s_scan[tid - off] : 0;
        __syncthreads();
        s_scan[tid] += v;
        __syncthreads();
    }
    int offset = s_scan[tid] - c;
    int total  = s_scan[255];

    for (int j = 0; j < c; j++) {
        int e   = local[j];
        int pos = offset + j;
        if (pos < NODE_CAP) g_node_edges[n * NODE_CAP + pos] = e;
        int q = atomicAdd(&g_edge_cnt[e], 1);
        if (q < EDGE_CAP) g_edge_nodes[e * EDGE_CAP + q] = n;
    }
    if (tid == 0) g_node_cnt[n] = min(total, NODE_CAP);
}

// ---------------- kernel: nodesum[n] = sum_{e in list(n)} s[e] ---------------
__global__ void __launch_bounds__(128)
node_sum_kernel() {
    const int n = blockIdx.x;
    const int d = threadIdx.x;
    const int cnt = g_node_cnt[n];
    const int* lst = &g_node_edges[n * NODE_CAP];

    float a0 = 0.f, a1 = 0.f, a2 = 0.f, a3 = 0.f;
    int i = 0;
    for (; i + 4 <= cnt; i += 4) {
        int e0 = lst[i], e1 = lst[i + 1], e2 = lst[i + 2], e3 = lst[i + 3];
        a0 += g_s[(size_t)e0 * 128 + d];
        a1 += g_s[(size_t)e1 * 128 + d];
        a2 += g_s[(size_t)e2 * 128 + d];
        a3 += g_s[(size_t)e3 * 128 + d];
    }
    for (; i < cnt; i++) a0 += g_s[(size_t)lst[i] * 128 + d];
    g_nodesum[n * 128 + d] = (a0 + a1) + (a2 + a3);
}

// ---------------- kernel: agg + concat, written pre-split bf16 ---------------
// 4 independent accumulator chains over the rank-sorted node list break the
// serial L2-latency dependency (the old single-acc loop cost ~10 x 240 cyc
// per edge). Order is a fixed function of the sorted list -> deterministic.
__global__ void __launch_bounds__(128)
edge_gather_kernel(const float* __restrict__ feature) {
    const int e   = blockIdx.x;
    const int tid = threadIdx.x;

    __shared__ int sl[EDGE_CAP];
    __shared__ int ss[EDGE_CAP];
    const int cnt = min(g_edge_cnt[e], EDGE_CAP);

    if (tid < cnt) sl[tid] = g_edge_nodes[e * EDGE_CAP + tid];
    __syncthreads();
    if (tid < cnt) {
        int v = sl[tid];
        int r = 0;
        for (int j = 0; j < cnt; j++) r += (sl[j] < v);
        ss[r] = v;   // node ids unique per edge -> ranks distinct
    }
    __syncthreads();

    float a0 = -g_s[(size_t)e * 128 + tid];
    float a1 = 0.f, a2 = 0.f, a3 = 0.f;
    int i = 0;
    for (; i + 4 <= cnt; i += 4) {
        int n0 = ss[i], n1 = ss[i + 1], n2 = ss[i + 2], n3 = ss[i + 3];
        a0 += g_nodesum[n0 * 128 + tid];
        a1 += g_nodesum[n1 * 128 + tid];
        a2 += g_nodesum[n2 * 128 + tid];
        a3 += g_nodesum[n3 * 128 + tid];
    }
    for (; i < cnt; i++) a0 += g_nodesum[ss[i] * 128 + tid];
    float acc = (a0 + a1) + (a2 + a3);
    {
        __nv_bfloat16 h = __float2bfloat16(acc);
        g_agg_hi[(size_t)e * D_CAT + tid] = h;
        g_agg_lo[(size_t)e * D_CAT + tid] = __float2bfloat16(acc - __bfloat162float(h));
    }
    if (tid < D_FEAT) {
        float f = feature[(size_t)e * D_FEAT + tid];
        __nv_bfloat16 h = __float2bfloat16(f);
        g_agg_hi[(size_t)e * D_CAT + 128 + tid] = h;
        g_agg_lo[(size_t)e * D_CAT + 128 + tid] = __float2bfloat16(f - __bfloat162float(h));
    }
}

// ---------------- launch -----------------------------------------------------
extern "C" void kernel_launch(void* const* d_in, const int* in_sizes, int n_in,
                              void* d_out, int out_size) {
    const float* state   = (const float*)d_in[0];
    const float* feature = (const float*)d_in[1];
    const float* mask    = (const float*)d_in[2];
    // d_in[3] = mask_transpose (unused: exactly mask.T)
    const float* W1_m    = (const float*)d_in[4];
    const float* b1_m    = (const float*)d_in[5];
    const float* W2_m    = (const float*)d_in[6];
    const float* W1_a    = (const float*)d_in[7];
    const float* b1_a    = (const float*)d_in[8];
    const float* W2_a    = (const float*)d_in[9];
    float* out = (float*)d_out;

    // smem: 512 + 2*A(64*LDK1*2) + 2*W(128*LDK1*2)
    const int SMEM_A = 512 + 2 * (64 * 136 * 2) + 2 * (128 * 136 * 2);  // 104,960
    const int SMEM_B = 512 + 2 * (64 * 168 * 2) + 2 * (128 * 168 * 2);  // 129,536
    cudaFuncSetAttribute((const void*)fused_mlp_kernel<128, true>,
                         cudaFuncAttributeMaxDynamicSharedMemorySize, SMEM_A);
    cudaFuncSetAttribute((const void*)fused_mlp_kernel<160, false>,
                         cudaFuncAttributeMaxDynamicSharedMemorySize, SMEM_B);

    float* d_s = nullptr;
    __nv_bfloat16 *d_agg_hi = nullptr, *d_agg_lo = nullptr;
    __nv_bfloat16 *d_w1mh = nullptr, *d_w1ml = nullptr, *d_w2mh = nullptr, *d_w2ml = nullptr;
    __nv_bfloat16 *d_w1ah = nullptr, *d_w1al = nullptr, *d_w2ah = nullptr, *d_w2al = nullptr;
    cudaGetSymbolAddress((void**)&d_s, g_s);
    cudaGetSymbolAddress((void**)&d_agg_hi, g_agg_hi);
    cudaGetSymbolAddress((void**)&d_agg_lo, g_agg_lo);
    cudaGetSymbolAddress((void**)&d_w1mh, g_w1m_hi);
    cudaGetSymbolAddress((void**)&d_w1ml, g_w1m_lo);
    cudaGetSymbolAddress((void**)&d_w2mh, g_w2m_hi);
    cudaGetSymbolAddress((void**)&d_w2ml, g_w2m_lo);
    cudaGetSymbolAddress((void**)&d_w1ah, g_w1a_hi);
    cudaGetSymbolAddress((void**)&d_w1al, g_w1a_lo);
    cudaGetSymbolAddress((void**)&d_w2ah, g_w2a_hi);
    cudaGetSymbolAddress((void**)&d_w2al, g_w2a_lo);

    const int GB = N_EDGES / 64;   // 512 CTAs per fused MLP

    // Fork a side branch for the mask scan (cost-free; kept from R13).
    // Host objects leak (kernel_launch runs only for correctness + capture;
    // graph replays never re-enter host code).
    cudaStream_t s2;
    cudaStreamCreateWithFlags(&s2, cudaStreamNonBlocking);
    cudaEvent_t evFork, evJoin;
    cudaEventCreateWithFlags(&evFork, cudaEventDisableTiming);
    cudaEventCreateWithFlags(&evJoin, cudaEventDisableTiming);

    // --- fork: branch A (mask scan) on s2 ---
    cudaEventRecord(evFork, 0);
    cudaStreamWaitEvent(s2, evFork, 0);
    zero_edge_cnt_kernel<<<N_EDGES / 256, 256, 0, s2>>>();
    build_lists_kernel<<<N_NODES, 256, 0, s2>>>(mask);
    cudaEventRecord(evJoin, s2);

    // --- branch B (memory MLP) on the main stream ---
    prep_weights_kernel<<<(128 * 160 + 255) / 256, 256>>>(W1_m, W2_m, W1_a, W2_a);
    fused_mlp_kernel<128, true><<<GB, 256, SMEM_A>>>(
        state, nullptr, nullptr, d_w1mh, d_w1ml, b1_m, d_w2mh, d_w2ml, d_s);

    // --- join: aggregation needs both lists (A) and s (B) ---
    cudaStreamWaitEvent(0, evJoin, 0);
    node_sum_kernel<<<N_NODES, 128>>>();
    edge_gather_kernel<<<N_EDGES, 128>>>(feature);

    // aggregation MLP (fused 2 layers): out = ls(ls(agg@W1a^T+b1a)@W2a^T)
    fused_mlp_kernel<160, false><<<GB, 256, SMEM_B>>>(
        nullptr, d_agg_hi, d_agg_lo, d_w1ah, d_w1al, b1_a, d_w2ah, d_w2al, out);
}